// round 3
// baseline (speedup 1.0000x reference)
#include <cuda_runtime.h>
#include <cstdint>

// Embedding gather: out[t, :] = weights[ids[t], :]
// ids: [4,4096] int32 (16384 tokens), weights: [50257,1024] fp32, out: [16384,1024] fp32
//
// One thread per float4 (16 bytes). Row = 1024 floats = 256 float4.
// 16384 tokens * 256 = 4,194,304 threads.

static constexpr int ROW_F4 = 256;   // float4 per embedding row (1024 floats)

__global__ void embed_gather_kernel(const int* __restrict__ ids,
                                    const float4* __restrict__ w,
                                    float4* __restrict__ out,
                                    int n_tokens)
{
    int idx = blockIdx.x * blockDim.x + threadIdx.x;   // which float4 of output
    int tok = idx >> 8;        // idx / ROW_F4
    int col = idx & (ROW_F4 - 1);
    if (tok < n_tokens) {
        int row = __ldg(ids + tok);                    // broadcast within 256-thread group
        out[idx] = __ldg(w + (size_t)row * ROW_F4 + col);
    }
}

extern "C" void kernel_launch(void* const* d_in, const int* in_sizes, int n_in,
                              void* d_out, int out_size)
{
    const int*    ids = (const int*)d_in[0];      // token_ids, int32, 16384 elems
    const float4* w   = (const float4*)d_in[1];   // weights,  fp32, 50257*1024 elems
    float4*       out = (float4*)d_out;           // [16384, 1024] fp32

    int n_tokens = in_sizes[0];                   // 16384
    long long total_f4 = (long long)n_tokens * ROW_F4;

    int threads = 256;
    int blocks  = (int)((total_f4 + threads - 1) / threads);
    embed_gather_kernel<<<blocks, threads>>>(ids, w, out, n_tokens);
}

// round 4
// speedup vs baseline: 1.4697x; 1.4697x over previous
#include <cuda_runtime.h>
#include <cstdint>

// Embedding gather: out[t, :] = weights[ids[t], :]
// ids: 16384 tokens int32, weights: [50257,1024] fp32, out: [16384,1024] fp32
//
// Block = 256 threads = one float4-column each; each block handles 4 tokens,
// giving every thread 4 independent LDG.128 in flight (MLP_p1=4) before any
// store. Stores use .cs (streaming) to keep L2 for the gathered weight rows.

static constexpr int ROW_F4       = 256;  // float4 per row (1024 floats)
static constexpr int TOK_PER_BLK  = 4;

__global__ void __launch_bounds__(256) embed_gather_kernel(
    const int* __restrict__ ids,
    const float4* __restrict__ w,
    float4* __restrict__ out,
    int n_tokens)
{
    const int col  = threadIdx.x;                 // 0..255
    const int tok0 = blockIdx.x * TOK_PER_BLK;

    if (tok0 + TOK_PER_BLK <= n_tokens) {
        // fast path: fully unrolled, 4 independent gathers
        const int r0 = __ldg(ids + tok0 + 0);
        const int r1 = __ldg(ids + tok0 + 1);
        const int r2 = __ldg(ids + tok0 + 2);
        const int r3 = __ldg(ids + tok0 + 3);

        float4 v0 = __ldg(w + (size_t)r0 * ROW_F4 + col);
        float4 v1 = __ldg(w + (size_t)r1 * ROW_F4 + col);
        float4 v2 = __ldg(w + (size_t)r2 * ROW_F4 + col);
        float4 v3 = __ldg(w + (size_t)r3 * ROW_F4 + col);

        __stcs(out + (size_t)(tok0 + 0) * ROW_F4 + col, v0);
        __stcs(out + (size_t)(tok0 + 1) * ROW_F4 + col, v1);
        __stcs(out + (size_t)(tok0 + 2) * ROW_F4 + col, v2);
        __stcs(out + (size_t)(tok0 + 3) * ROW_F4 + col, v3);
    } else {
        for (int t = tok0; t < n_tokens; ++t) {
            int r = __ldg(ids + t);
            __stcs(out + (size_t)t * ROW_F4 + col,
                   __ldg(w + (size_t)r * ROW_F4 + col));
        }
    }
}

extern "C" void kernel_launch(void* const* d_in, const int* in_sizes, int n_in,
                              void* d_out, int out_size)
{
    const int*    ids = (const int*)d_in[0];
    const float4* w   = (const float4*)d_in[1];
    float4*       out = (float4*)d_out;

    int n_tokens = in_sizes[0];                       // 16384
    int blocks   = (n_tokens + TOK_PER_BLK - 1) / TOK_PER_BLK;  // 4096
    embed_gather_kernel<<<blocks, 256>>>(ids, w, out, n_tokens);
}